// round 1
// baseline (speedup 1.0000x reference)
#include <cuda_runtime.h>
#include <cuda_bf16.h>

// Problem constants (fixed dataset): N=50000, E=800000, IN_F=256, OUT_F=64, HEADS=8
#define IN_F 256
#define OUT_F 64
#define MAXN 50000
#define MAXE 800000

// Static device scratch (no allocation allowed)
__device__ float g_hp[MAXN * OUT_F];      // projected features [N, 64]
__device__ int   g_counts[MAXN];          // in-degree histogram
__device__ int   g_offsets[MAXN + 1];     // CSR offsets by dst
__device__ int   g_cursors[MAXN];         // scatter cursors
__device__ int   g_esrc[MAXE];            // src node id per edge, bucketed by dst

// ---------------------------------------------------------------------------
// K0: zero the histogram
// ---------------------------------------------------------------------------
__global__ void zero_counts_kernel(int n) {
    int i = blockIdx.x * blockDim.x + threadIdx.x;
    if (i < n) g_counts[i] = 0;
}

// ---------------------------------------------------------------------------
// K1: GEMM hp = h @ W   (h: [n,256] row-major, W: [256,64] row-major)
// Tile: 32 rows x 64 cols per block, 128 threads, each thread 4 rows x 4 cols.
// ---------------------------------------------------------------------------
#define G_ROWS 32
#define G_THREADS 128
#define G_PITCH (IN_F + 4)   // padded smem row pitch (floats), keeps float4 align

__global__ __launch_bounds__(G_THREADS)
void gemm_kernel(const float* __restrict__ h, const float* __restrict__ W, int n) {
    __shared__ float sh[G_ROWS * G_PITCH];

    int block_row = blockIdx.x * G_ROWS;

    // Cooperative load of the h tile: 32 rows x 256 floats = 8192 floats,
    // 128 threads -> 64 floats (16 float4) each.
    for (int i = threadIdx.x; i < G_ROWS * (IN_F / 4); i += G_THREADS) {
        int r  = i / (IN_F / 4);
        int c4 = (i % (IN_F / 4)) * 4;
        float4 v = make_float4(0.f, 0.f, 0.f, 0.f);
        int gr = block_row + r;
        if (gr < n) v = *(const float4*)&h[(size_t)gr * IN_F + c4];
        *(float4*)&sh[r * G_PITCH + c4] = v;
    }
    __syncthreads();

    int tx = threadIdx.x & 15;   // col group (16 groups of 4 cols = 64 cols)
    int ty = threadIdx.x >> 4;   // row group (8 groups of 4 rows = 32 rows)
    int col  = tx * 4;
    int row0 = ty * 4;

    float acc[4][4];
#pragma unroll
    for (int i = 0; i < 4; i++)
#pragma unroll
        for (int j = 0; j < 4; j++) acc[i][j] = 0.f;

#pragma unroll 4
    for (int k = 0; k < IN_F; k++) {
        float4 w = *(const float4*)&W[k * OUT_F + col];  // L1/L2 resident (64KB)
        float hv[4];
#pragma unroll
        for (int i = 0; i < 4; i++) hv[i] = sh[(row0 + i) * G_PITCH + k];
#pragma unroll
        for (int i = 0; i < 4; i++) {
            acc[i][0] = fmaf(hv[i], w.x, acc[i][0]);
            acc[i][1] = fmaf(hv[i], w.y, acc[i][1]);
            acc[i][2] = fmaf(hv[i], w.z, acc[i][2]);
            acc[i][3] = fmaf(hv[i], w.w, acc[i][3]);
        }
    }

#pragma unroll
    for (int i = 0; i < 4; i++) {
        int gr = block_row + row0 + i;
        if (gr < n) {
            *(float4*)&g_hp[(size_t)gr * OUT_F + col] =
                make_float4(acc[i][0], acc[i][1], acc[i][2], acc[i][3]);
        }
    }
}

// ---------------------------------------------------------------------------
// K2: histogram of dst
// ---------------------------------------------------------------------------
__global__ void hist_kernel(const int* __restrict__ dst, int e) {
    int i = blockIdx.x * blockDim.x + threadIdx.x;
    if (i < e) atomicAdd(&g_counts[dst[i]], 1);
}

// ---------------------------------------------------------------------------
// K3: single-block exclusive scan of counts -> offsets (+ cursors copy)
// 1024 threads, each owns a contiguous chunk; two-level warp shfl scan.
// ---------------------------------------------------------------------------
__global__ __launch_bounds__(1024)
void scan_kernel(int n) {
    const int T = 1024;
    int t = threadIdx.x;
    int chunk = (n + T - 1) / T;
    int start = t * chunk;
    int end   = start + chunk; if (end > n) end = n;
    if (start > n) start = n;

    int local = 0;
    for (int i = start; i < end; i++) local += g_counts[i];

    __shared__ int warp_sums[32];
    int lane = t & 31, wid = t >> 5;
    int v = local;
#pragma unroll
    for (int o = 1; o < 32; o <<= 1) {
        int x = __shfl_up_sync(0xFFFFFFFFu, v, o);
        if (lane >= o) v += x;
    }
    if (lane == 31) warp_sums[wid] = v;
    __syncthreads();
    if (wid == 0) {
        int s = warp_sums[lane];
#pragma unroll
        for (int o = 1; o < 32; o <<= 1) {
            int x = __shfl_up_sync(0xFFFFFFFFu, s, o);
            if (lane >= o) s += x;
        }
        warp_sums[lane] = s;
    }
    __syncthreads();

    int excl_thread = (v - local) + (wid > 0 ? warp_sums[wid - 1] : 0);

    int run = excl_thread;
    for (int i = start; i < end; i++) {
        g_offsets[i] = run;
        g_cursors[i] = run;
        run += g_counts[i];
    }
    if (t == T - 1) g_offsets[n] = run;   // total (chunk may be empty; still correct)
}

// ---------------------------------------------------------------------------
// K4: scatter edges into CSR buckets by dst
// ---------------------------------------------------------------------------
__global__ void scatter_kernel(const int* __restrict__ src,
                               const int* __restrict__ dst, int e) {
    int i = blockIdx.x * blockDim.x + threadIdx.x;
    if (i < e) {
        int p = atomicAdd(&g_cursors[dst[i]], 1);
        g_esrc[p] = src[i];
    }
}

// ---------------------------------------------------------------------------
// K5: warp-per-destination-node aggregation.
// out[n] = (deg>0) ? c * sum_{e: dst=n} dot(hs,hd)*hs  :  hp[n]
// ---------------------------------------------------------------------------
__global__ __launch_bounds__(256)
void aggregate_kernel(const float* __restrict__ aw, int n_aw,
                      float* __restrict__ out, int n) {
    int warp = (blockIdx.x * blockDim.x + threadIdx.x) >> 5;
    int lane = threadIdx.x & 31;
    if (warp >= n) return;

    float c = 0.f;
    for (int i = 0; i < n_aw; i++) c += __ldg(&aw[i]);

    const float* __restrict__ hp = g_hp;
    float hd0 = hp[warp * OUT_F + lane];
    float hd1 = hp[warp * OUT_F + 32 + lane];

    int beg = g_offsets[warp];
    int fin = g_offsets[warp + 1];

    float a0 = 0.f, a1 = 0.f;
    int e = beg;
    // 2-way edge ILP to overlap the L2 gather + shuffle-reduce chains
    for (; e + 1 < fin; e += 2) {
        int s0 = g_esrc[e];
        int s1 = g_esrc[e + 1];
        const float* r0 = hp + (size_t)s0 * OUT_F;
        const float* r1 = hp + (size_t)s1 * OUT_F;
        float x0 = r0[lane], x1 = r0[32 + lane];
        float y0 = r1[lane], y1 = r1[32 + lane];
        float p = fmaf(x0, hd0, x1 * hd1);
        float q = fmaf(y0, hd0, y1 * hd1);
#pragma unroll
        for (int o = 16; o > 0; o >>= 1) {
            p += __shfl_xor_sync(0xFFFFFFFFu, p, o);
            q += __shfl_xor_sync(0xFFFFFFFFu, q, o);
        }
        a0 = fmaf(p, x0, a0);
        a1 = fmaf(p, x1, a1);
        a0 = fmaf(q, y0, a0);
        a1 = fmaf(q, y1, a1);
    }
    if (e < fin) {
        int s0 = g_esrc[e];
        const float* r0 = hp + (size_t)s0 * OUT_F;
        float x0 = r0[lane], x1 = r0[32 + lane];
        float p = fmaf(x0, hd0, x1 * hd1);
#pragma unroll
        for (int o = 16; o > 0; o >>= 1)
            p += __shfl_xor_sync(0xFFFFFFFFu, p, o);
        a0 = fmaf(p, x0, a0);
        a1 = fmaf(p, x1, a1);
    }

    if (fin > beg) {
        out[warp * OUT_F + lane]      = c * a0;
        out[warp * OUT_F + 32 + lane] = c * a1;
    } else {
        out[warp * OUT_F + lane]      = hd0;
        out[warp * OUT_F + 32 + lane] = hd1;
    }
}

// ---------------------------------------------------------------------------
extern "C" void kernel_launch(void* const* d_in, const int* in_sizes, int n_in,
                              void* d_out, int out_size) {
    const float* h   = (const float*)d_in[0];
    const float* W   = (const float*)d_in[1];
    const float* aw  = (const float*)d_in[2];
    const int*   src = (const int*)d_in[3];
    const int*   dst = (const int*)d_in[4];
    float* out = (float*)d_out;

    int n    = in_sizes[0] / IN_F;   // 50000
    int e    = in_sizes[3];          // 800000
    int n_aw = in_sizes[2];          // 8

    zero_counts_kernel<<<(n + 255) / 256, 256>>>(n);
    gemm_kernel<<<(n + G_ROWS - 1) / G_ROWS, G_THREADS>>>(h, W, n);
    hist_kernel<<<(e + 255) / 256, 256>>>(dst, e);
    scan_kernel<<<1, 1024>>>(n);
    scatter_kernel<<<(e + 255) / 256, 256>>>(src, dst, e);
    aggregate_kernel<<<((n * 32) + 255) / 256, 256>>>(aw, n_aw, out, n);
}

// round 2
// speedup vs baseline: 1.6075x; 1.6075x over previous
#include <cuda_runtime.h>
#include <cuda_bf16.h>

// Problem constants (fixed dataset): N=50000, E=800000, IN_F=256, OUT_F=64, HEADS=8
#define IN_F 256
#define OUT_F 64
#define MAXN 50000
#define MAXE 800000

// Static device scratch (no allocation allowed)
__device__ float g_hp[MAXN * OUT_F];      // projected features [N, 64]
__device__ int   g_counts[MAXN];          // in-degree histogram
__device__ int   g_offsets[MAXN + 1];     // CSR offsets by dst
__device__ int   g_cursors[MAXN];         // scatter cursors
__device__ int   g_esrc[MAXE];            // src node id per edge, bucketed by dst

// Multi-block scan config
#define SCAN_T 256
#define SCAN_E 4
#define SCAN_CHUNK (SCAN_T * SCAN_E)                       // 1024 elems / block
#define SCAN_B ((MAXN + SCAN_CHUNK - 1) / SCAN_CHUNK)      // 49 blocks
__device__ int g_bsum[SCAN_B + 1];

// ---------------------------------------------------------------------------
// K0: zero the histogram
// ---------------------------------------------------------------------------
__global__ void zero_counts_kernel(int n) {
    int i = blockIdx.x * blockDim.x + threadIdx.x;
    if (i < n) g_counts[i] = 0;
}

// ---------------------------------------------------------------------------
// K1: GEMM hp = h @ W   (h: [n,256] row-major, W: [256,64] row-major)
// Tile: 32 rows x 64 cols per block, 128 threads, each thread 4 rows x 4 cols.
// ---------------------------------------------------------------------------
#define G_ROWS 32
#define G_THREADS 128
#define G_PITCH (IN_F + 4)   // padded smem row pitch (floats), keeps float4 align

__global__ __launch_bounds__(G_THREADS)
void gemm_kernel(const float* __restrict__ h, const float* __restrict__ W, int n) {
    __shared__ float sh[G_ROWS * G_PITCH];

    int block_row = blockIdx.x * G_ROWS;

    for (int i = threadIdx.x; i < G_ROWS * (IN_F / 4); i += G_THREADS) {
        int r  = i / (IN_F / 4);
        int c4 = (i % (IN_F / 4)) * 4;
        float4 v = make_float4(0.f, 0.f, 0.f, 0.f);
        int gr = block_row + r;
        if (gr < n) v = *(const float4*)&h[(size_t)gr * IN_F + c4];
        *(float4*)&sh[r * G_PITCH + c4] = v;
    }
    __syncthreads();

    int tx = threadIdx.x & 15;   // col group (16 groups of 4 cols = 64 cols)
    int ty = threadIdx.x >> 4;   // row group (8 groups of 4 rows = 32 rows)
    int col  = tx * 4;
    int row0 = ty * 4;

    float acc[4][4];
#pragma unroll
    for (int i = 0; i < 4; i++)
#pragma unroll
        for (int j = 0; j < 4; j++) acc[i][j] = 0.f;

#pragma unroll 4
    for (int k = 0; k < IN_F; k++) {
        float4 w = *(const float4*)&W[k * OUT_F + col];  // L1/L2 resident (64KB)
        float hv[4];
#pragma unroll
        for (int i = 0; i < 4; i++) hv[i] = sh[(row0 + i) * G_PITCH + k];
#pragma unroll
        for (int i = 0; i < 4; i++) {
            acc[i][0] = fmaf(hv[i], w.x, acc[i][0]);
            acc[i][1] = fmaf(hv[i], w.y, acc[i][1]);
            acc[i][2] = fmaf(hv[i], w.z, acc[i][2]);
            acc[i][3] = fmaf(hv[i], w.w, acc[i][3]);
        }
    }

#pragma unroll
    for (int i = 0; i < 4; i++) {
        int gr = block_row + row0 + i;
        if (gr < n) {
            *(float4*)&g_hp[(size_t)gr * OUT_F + col] =
                make_float4(acc[i][0], acc[i][1], acc[i][2], acc[i][3]);
        }
    }
}

// ---------------------------------------------------------------------------
// K2: histogram of dst
// ---------------------------------------------------------------------------
__global__ void hist_kernel(const int* __restrict__ dst, int e) {
    int i = blockIdx.x * blockDim.x + threadIdx.x;
    if (i < e) atomicAdd(&g_counts[dst[i]], 1);
}

// ---------------------------------------------------------------------------
// K3a: block-local exclusive scan of counts. Writes local-exclusive prefix to
// g_offsets[i] (base added later) and the block total to g_bsum[b].
// ---------------------------------------------------------------------------
__global__ __launch_bounds__(SCAN_T)
void scan_local_kernel(int n) {
    __shared__ int warp_sums[SCAN_T / 32];
    int t    = threadIdx.x;
    int base = blockIdx.x * SCAN_CHUNK + t * SCAN_E;

    int v[SCAN_E];
#pragma unroll
    for (int i = 0; i < SCAN_E; i++)
        v[i] = (base + i < n) ? g_counts[base + i] : 0;

    int tsum = 0;
#pragma unroll
    for (int i = 0; i < SCAN_E; i++) tsum += v[i];

    // warp inclusive scan of thread sums
    int lane = t & 31, wid = t >> 5;
    int incl = tsum;
#pragma unroll
    for (int o = 1; o < 32; o <<= 1) {
        int x = __shfl_up_sync(0xFFFFFFFFu, incl, o);
        if (lane >= o) incl += x;
    }
    if (lane == 31) warp_sums[wid] = incl;
    __syncthreads();
    if (wid == 0) {
        int s = (lane < SCAN_T / 32) ? warp_sums[lane] : 0;
#pragma unroll
        for (int o = 1; o < SCAN_T / 32; o <<= 1) {
            int x = __shfl_up_sync(0xFFFFFFFFu, s, o);
            if (lane >= o) s += x;
        }
        if (lane < SCAN_T / 32) warp_sums[lane] = s;
    }
    __syncthreads();

    int texcl = (incl - tsum) + (wid > 0 ? warp_sums[wid - 1] : 0);

    int run = texcl;
#pragma unroll
    for (int i = 0; i < SCAN_E; i++) {
        if (base + i < n) g_offsets[base + i] = run;
        run += v[i];
    }
    if (t == SCAN_T - 1) g_bsum[blockIdx.x] = warp_sums[SCAN_T / 32 - 1];
}

// ---------------------------------------------------------------------------
// K3b: spine scan (SCAN_B=49 values) in one small block.
// ---------------------------------------------------------------------------
__global__ __launch_bounds__(64)
void scan_spine_kernel() {
    __shared__ int sm[64];
    int t = threadIdx.x;
    int v = (t < SCAN_B) ? g_bsum[t] : 0;
    sm[t] = v;
    __syncthreads();
    int incl = v;
#pragma unroll
    for (int o = 1; o < 64; o <<= 1) {
        int add = (t >= o) ? sm[t - o] : 0;
        __syncthreads();
        incl += add;
        sm[t] = incl;
        __syncthreads();
    }
    if (t < SCAN_B) g_bsum[t] = incl - v;     // exclusive
    if (t == 63)    g_bsum[SCAN_B] = sm[63];  // total
}

// ---------------------------------------------------------------------------
// K3c: add spine base, finalize offsets + cursors, write sentinel.
// ---------------------------------------------------------------------------
__global__ __launch_bounds__(SCAN_T)
void scan_add_kernel(int n) {
    int b    = blockIdx.x;
    int boff = g_bsum[b];
    int base = b * SCAN_CHUNK + threadIdx.x * SCAN_E;
#pragma unroll
    for (int i = 0; i < SCAN_E; i++) {
        int idx = base + i;
        if (idx < n) {
            int o = g_offsets[idx] + boff;
            g_offsets[idx] = o;
            g_cursors[idx] = o;
        }
    }
    if (b == 0 && threadIdx.x == 0) g_offsets[n] = g_bsum[SCAN_B];
}

// ---------------------------------------------------------------------------
// K4: scatter edges into CSR buckets by dst
// ---------------------------------------------------------------------------
__global__ void scatter_kernel(const int* __restrict__ src,
                               const int* __restrict__ dst, int e) {
    int i = blockIdx.x * blockDim.x + threadIdx.x;
    if (i < e) {
        int p = atomicAdd(&g_cursors[dst[i]], 1);
        g_esrc[p] = src[i];
    }
}

// ---------------------------------------------------------------------------
// K5: warp-per-destination-node aggregation.
// out[n] = (deg>0) ? c * sum_{e: dst=n} dot(hs,hd)*hs  :  hp[n]
// ---------------------------------------------------------------------------
__global__ __launch_bounds__(256)
void aggregate_kernel(const float* __restrict__ aw, int n_aw,
                      float* __restrict__ out, int n) {
    int warp = (blockIdx.x * blockDim.x + threadIdx.x) >> 5;
    int lane = threadIdx.x & 31;
    if (warp >= n) return;

    float c = 0.f;
    for (int i = 0; i < n_aw; i++) c += __ldg(&aw[i]);

    const float* __restrict__ hp = g_hp;
    float hd0 = hp[warp * OUT_F + lane];
    float hd1 = hp[warp * OUT_F + 32 + lane];

    int beg = g_offsets[warp];
    int fin = g_offsets[warp + 1];

    float a0 = 0.f, a1 = 0.f;
    int e = beg;
    // 2-way edge ILP to overlap the L2 gather + shuffle-reduce chains
    for (; e + 1 < fin; e += 2) {
        int s0 = g_esrc[e];
        int s1 = g_esrc[e + 1];
        const float* r0 = hp + (size_t)s0 * OUT_F;
        const float* r1 = hp + (size_t)s1 * OUT_F;
        float x0 = r0[lane], x1 = r0[32 + lane];
        float y0 = r1[lane], y1 = r1[32 + lane];
        float p = fmaf(x0, hd0, x1 * hd1);
        float q = fmaf(y0, hd0, y1 * hd1);
#pragma unroll
        for (int o = 16; o > 0; o >>= 1) {
            p += __shfl_xor_sync(0xFFFFFFFFu, p, o);
            q += __shfl_xor_sync(0xFFFFFFFFu, q, o);
        }
        a0 = fmaf(p, x0, a0);
        a1 = fmaf(p, x1, a1);
        a0 = fmaf(q, y0, a0);
        a1 = fmaf(q, y1, a1);
    }
    if (e < fin) {
        int s0 = g_esrc[e];
        const float* r0 = hp + (size_t)s0 * OUT_F;
        float x0 = r0[lane], x1 = r0[32 + lane];
        float p = fmaf(x0, hd0, x1 * hd1);
#pragma unroll
        for (int o = 16; o > 0; o >>= 1)
            p += __shfl_xor_sync(0xFFFFFFFFu, p, o);
        a0 = fmaf(p, x0, a0);
        a1 = fmaf(p, x1, a1);
    }

    if (fin > beg) {
        out[warp * OUT_F + lane]      = c * a0;
        out[warp * OUT_F + 32 + lane] = c * a1;
    } else {
        out[warp * OUT_F + lane]      = hd0;
        out[warp * OUT_F + 32 + lane] = hd1;
    }
}

// ---------------------------------------------------------------------------
extern "C" void kernel_launch(void* const* d_in, const int* in_sizes, int n_in,
                              void* d_out, int out_size) {
    const float* h   = (const float*)d_in[0];
    const float* W   = (const float*)d_in[1];
    const float* aw  = (const float*)d_in[2];
    const int*   src = (const int*)d_in[3];
    const int*   dst = (const int*)d_in[4];
    float* out = (float*)d_out;

    int n    = in_sizes[0] / IN_F;   // 50000
    int e    = in_sizes[3];          // 800000
    int n_aw = in_sizes[2];          // 8

    zero_counts_kernel<<<(n + 255) / 256, 256>>>(n);
    gemm_kernel<<<(n + G_ROWS - 1) / G_ROWS, G_THREADS>>>(h, W, n);
    hist_kernel<<<(e + 255) / 256, 256>>>(dst, e);
    scan_local_kernel<<<SCAN_B, SCAN_T>>>(n);
    scan_spine_kernel<<<1, 64>>>();
    scan_add_kernel<<<SCAN_B, SCAN_T>>>(n);
    scatter_kernel<<<(e + 255) / 256, 256>>>(src, dst, e);
    aggregate_kernel<<<((n * 32) + 255) / 256, 256>>>(aw, n_aw, out, n);
}

// round 3
// speedup vs baseline: 1.6465x; 1.0243x over previous
#include <cuda_runtime.h>
#include <cuda_bf16.h>

// Problem constants (fixed dataset): N=50000, E=800000, IN_F=256, OUT_F=64, HEADS=8
#define IN_F 256
#define OUT_F 64
#define MAXN 50000
#define MAXE 800000

// Static device scratch (no allocation allowed)
__device__ float g_hp[MAXN * OUT_F];      // projected features [N, 64]
__device__ int   g_counts[MAXN];          // in-degree histogram
__device__ int   g_offsets[MAXN + 1];     // CSR offsets by dst
__device__ int   g_cursors[MAXN];         // scatter cursors
__device__ int   g_esrc[MAXE];            // src node id per edge, bucketed by dst

// Multi-block scan config
#define SCAN_T 256
#define SCAN_E 4
#define SCAN_CHUNK (SCAN_T * SCAN_E)                       // 1024 elems / block
#define SCAN_B ((MAXN + SCAN_CHUNK - 1) / SCAN_CHUNK)      // 49 blocks
__device__ int g_bsum[SCAN_B + 1];

// Packed fp32x2 helpers (Blackwell sm_100+; ptxas will not auto-fuse these)
#define FMA_F32X2(d, a, b, c) \
    asm("fma.rn.f32x2 %0, %1, %2, %3;" : "=l"(d) : "l"(a), "l"(b), "l"(c))
#define PACK2(out, lo, hi) \
    asm("mov.b64 %0, {%1, %2};" : "=l"(out) : "f"(lo), "f"(hi))
#define UNPACK2(lo, hi, in) \
    asm("mov.b64 {%0, %1}, %2;" : "=f"(lo), "=f"(hi) : "l"(in))

// ---------------------------------------------------------------------------
// K0: zero the histogram
// ---------------------------------------------------------------------------
__global__ void zero_counts_kernel(int n) {
    int i = blockIdx.x * blockDim.x + threadIdx.x;
    if (i < n) g_counts[i] = 0;
}

// ---------------------------------------------------------------------------
// K1: GEMM hp = h @ W   (h: [n,256] row-major, W: [256,64] row-major)
// Tile: 32 rows x 64 cols per block, 128 threads, each thread 4 rows x 4 cols.
// Inner product uses packed fma.rn.f32x2 (2 fp32 FMA / instr on the fma pipe).
// ---------------------------------------------------------------------------
#define G_ROWS 32
#define G_THREADS 128
#define G_PITCH (IN_F + 4)   // padded smem row pitch (floats), keeps float4 align

__global__ __launch_bounds__(G_THREADS)
void gemm_kernel(const float* __restrict__ h, const float* __restrict__ W, int n) {
    __shared__ float sh[G_ROWS * G_PITCH];

    int block_row = blockIdx.x * G_ROWS;

    for (int i = threadIdx.x; i < G_ROWS * (IN_F / 4); i += G_THREADS) {
        int r  = i / (IN_F / 4);
        int c4 = (i % (IN_F / 4)) * 4;
        float4 v = make_float4(0.f, 0.f, 0.f, 0.f);
        int gr = block_row + r;
        if (gr < n) v = *(const float4*)&h[(size_t)gr * IN_F + c4];
        *(float4*)&sh[r * G_PITCH + c4] = v;
    }
    __syncthreads();

    int tx = threadIdx.x & 15;   // col group (16 groups of 4 cols = 64 cols)
    int ty = threadIdx.x >> 4;   // row group (8 groups of 4 rows = 32 rows)
    int col  = tx * 4;
    int row0 = ty * 4;

    // acc2[i][0] = cols (col, col+1), acc2[i][1] = cols (col+2, col+3), row row0+i
    unsigned long long acc2[4][2];
#pragma unroll
    for (int i = 0; i < 4; i++) { acc2[i][0] = 0ULL; acc2[i][1] = 0ULL; }

#pragma unroll 4
    for (int k = 0; k < IN_F; k++) {
        float4 w = *(const float4*)&W[k * OUT_F + col];  // L1-resident (64KB)
        unsigned long long w01, w23;
        PACK2(w01, w.x, w.y);
        PACK2(w23, w.z, w.w);
#pragma unroll
        for (int i = 0; i < 4; i++) {
            float hv = sh[(row0 + i) * G_PITCH + k];
            unsigned long long hv2;
            PACK2(hv2, hv, hv);
            FMA_F32X2(acc2[i][0], hv2, w01, acc2[i][0]);
            FMA_F32X2(acc2[i][1], hv2, w23, acc2[i][1]);
        }
    }

#pragma unroll
    for (int i = 0; i < 4; i++) {
        int gr = block_row + row0 + i;
        if (gr < n) {
            float4 o;
            UNPACK2(o.x, o.y, acc2[i][0]);
            UNPACK2(o.z, o.w, acc2[i][1]);
            *(float4*)&g_hp[(size_t)gr * OUT_F + col] = o;
        }
    }
}

// ---------------------------------------------------------------------------
// K2: histogram of dst
// ---------------------------------------------------------------------------
__global__ void hist_kernel(const int* __restrict__ dst, int e) {
    int i = blockIdx.x * blockDim.x + threadIdx.x;
    if (i < e) atomicAdd(&g_counts[dst[i]], 1);
}

// ---------------------------------------------------------------------------
// K3a: block-local exclusive scan of counts. Writes local-exclusive prefix to
// g_offsets[i] (base added later) and the block total to g_bsum[b].
// ---------------------------------------------------------------------------
__global__ __launch_bounds__(SCAN_T)
void scan_local_kernel(int n) {
    __shared__ int warp_sums[SCAN_T / 32];
    int t    = threadIdx.x;
    int base = blockIdx.x * SCAN_CHUNK + t * SCAN_E;

    int v[SCAN_E];
#pragma unroll
    for (int i = 0; i < SCAN_E; i++)
        v[i] = (base + i < n) ? g_counts[base + i] : 0;

    int tsum = 0;
#pragma unroll
    for (int i = 0; i < SCAN_E; i++) tsum += v[i];

    int lane = t & 31, wid = t >> 5;
    int incl = tsum;
#pragma unroll
    for (int o = 1; o < 32; o <<= 1) {
        int x = __shfl_up_sync(0xFFFFFFFFu, incl, o);
        if (lane >= o) incl += x;
    }
    if (lane == 31) warp_sums[wid] = incl;
    __syncthreads();
    if (wid == 0) {
        int s = (lane < SCAN_T / 32) ? warp_sums[lane] : 0;
#pragma unroll
        for (int o = 1; o < SCAN_T / 32; o <<= 1) {
            int x = __shfl_up_sync(0xFFFFFFFFu, s, o);
            if (lane >= o) s += x;
        }
        if (lane < SCAN_T / 32) warp_sums[lane] = s;
    }
    __syncthreads();

    int texcl = (incl - tsum) + (wid > 0 ? warp_sums[wid - 1] : 0);

    int run = texcl;
#pragma unroll
    for (int i = 0; i < SCAN_E; i++) {
        if (base + i < n) g_offsets[base + i] = run;
        run += v[i];
    }
    if (t == SCAN_T - 1) g_bsum[blockIdx.x] = warp_sums[SCAN_T / 32 - 1];
}

// ---------------------------------------------------------------------------
// K3b: spine scan (SCAN_B=49 values) in one small block.
// ---------------------------------------------------------------------------
__global__ __launch_bounds__(64)
void scan_spine_kernel() {
    __shared__ int sm[64];
    int t = threadIdx.x;
    int v = (t < SCAN_B) ? g_bsum[t] : 0;
    sm[t] = v;
    __syncthreads();
    int incl = v;
#pragma unroll
    for (int o = 1; o < 64; o <<= 1) {
        int add = (t >= o) ? sm[t - o] : 0;
        __syncthreads();
        incl += add;
        sm[t] = incl;
        __syncthreads();
    }
    if (t < SCAN_B) g_bsum[t] = incl - v;     // exclusive
    if (t == 63)    g_bsum[SCAN_B] = sm[63];  // total
}

// ---------------------------------------------------------------------------
// K3c: add spine base, finalize offsets + cursors, write sentinel.
// ---------------------------------------------------------------------------
__global__ __launch_bounds__(SCAN_T)
void scan_add_kernel(int n) {
    int b    = blockIdx.x;
    int boff = g_bsum[b];
    int base = b * SCAN_CHUNK + threadIdx.x * SCAN_E;
#pragma unroll
    for (int i = 0; i < SCAN_E; i++) {
        int idx = base + i;
        if (idx < n) {
            int o = g_offsets[idx] + boff;
            g_offsets[idx] = o;
            g_cursors[idx] = o;
        }
    }
    if (b == 0 && threadIdx.x == 0) g_offsets[n] = g_bsum[SCAN_B];
}

// ---------------------------------------------------------------------------
// K4: scatter edges into CSR buckets by dst
// ---------------------------------------------------------------------------
__global__ void scatter_kernel(const int* __restrict__ src,
                               const int* __restrict__ dst, int e) {
    int i = blockIdx.x * blockDim.x + threadIdx.x;
    if (i < e) {
        int p = atomicAdd(&g_cursors[dst[i]], 1);
        g_esrc[p] = src[i];
    }
}

// ---------------------------------------------------------------------------
// K5: warp-per-destination-node aggregation.
// out[n] = (deg>0) ? c * sum_{e: dst=n} dot(hs,hd)*hs  :  hp[n]
// ---------------------------------------------------------------------------
__global__ __launch_bounds__(256)
void aggregate_kernel(const float* __restrict__ aw, int n_aw,
                      float* __restrict__ out, int n) {
    int warp = (blockIdx.x * blockDim.x + threadIdx.x) >> 5;
    int lane = threadIdx.x & 31;
    if (warp >= n) return;

    float c = 0.f;
    for (int i = 0; i < n_aw; i++) c += __ldg(&aw[i]);

    const float* __restrict__ hp = g_hp;
    float hd0 = hp[warp * OUT_F + lane];
    float hd1 = hp[warp * OUT_F + 32 + lane];

    int beg = g_offsets[warp];
    int fin = g_offsets[warp + 1];

    float a0 = 0.f, a1 = 0.f;
    int e = beg;
    // 2-way edge ILP to overlap the L2 gather + shuffle-reduce chains
    for (; e + 1 < fin; e += 2) {
        int s0 = g_esrc[e];
        int s1 = g_esrc[e + 1];
        const float* r0 = hp + (size_t)s0 * OUT_F;
        const float* r1 = hp + (size_t)s1 * OUT_F;
        float x0 = r0[lane], x1 = r0[32 + lane];
        float y0 = r1[lane], y1 = r1[32 + lane];
        float p = fmaf(x0, hd0, x1 * hd1);
        float q = fmaf(y0, hd0, y1 * hd1);
#pragma unroll
        for (int o = 16; o > 0; o >>= 1) {
            p += __shfl_xor_sync(0xFFFFFFFFu, p, o);
            q += __shfl_xor_sync(0xFFFFFFFFu, q, o);
        }
        a0 = fmaf(p, x0, a0);
        a1 = fmaf(p, x1, a1);
        a0 = fmaf(q, y0, a0);
        a1 = fmaf(q, y1, a1);
    }
    if (e < fin) {
        int s0 = g_esrc[e];
        const float* r0 = hp + (size_t)s0 * OUT_F;
        float x0 = r0[lane], x1 = r0[32 + lane];
        float p = fmaf(x0, hd0, x1 * hd1);
#pragma unroll
        for (int o = 16; o > 0; o >>= 1)
            p += __shfl_xor_sync(0xFFFFFFFFu, p, o);
        a0 = fmaf(p, x0, a0);
        a1 = fmaf(p, x1, a1);
    }

    if (fin > beg) {
        out[warp * OUT_F + lane]      = c * a0;
        out[warp * OUT_F + 32 + lane] = c * a1;
    } else {
        out[warp * OUT_F + lane]      = hd0;
        out[warp * OUT_F + 32 + lane] = hd1;
    }
}

// ---------------------------------------------------------------------------
extern "C" void kernel_launch(void* const* d_in, const int* in_sizes, int n_in,
                              void* d_out, int out_size) {
    const float* h   = (const float*)d_in[0];
    const float* W   = (const float*)d_in[1];
    const float* aw  = (const float*)d_in[2];
    const int*   src = (const int*)d_in[3];
    const int*   dst = (const int*)d_in[4];
    float* out = (float*)d_out;

    int n    = in_sizes[0] / IN_F;   // 50000
    int e    = in_sizes[3];          // 800000
    int n_aw = in_sizes[2];          // 8

    zero_counts_kernel<<<(n + 255) / 256, 256>>>(n);
    gemm_kernel<<<(n + G_ROWS - 1) / G_ROWS, G_THREADS>>>(h, W, n);
    hist_kernel<<<(e + 255) / 256, 256>>>(dst, e);
    scan_local_kernel<<<SCAN_B, SCAN_T>>>(n);
    scan_spine_kernel<<<1, 64>>>();
    scan_add_kernel<<<SCAN_B, SCAN_T>>>(n);
    scatter_kernel<<<(e + 255) / 256, 256>>>(src, dst, e);
    aggregate_kernel<<<((n * 32) + 255) / 256, 256>>>(aw, n_aw, out, n);
}